// round 2
// baseline (speedup 1.0000x reference)
#include <cuda_runtime.h>
#include <cuda_bf16.h>
#include <cstdint>

// Problem constants (fixed by the reference):
//   x: [M, 4096] fp32 (M = 8192), cores build G: [4096, 4096], out = x @ G^T + bias
#define KDIM 4096
#define NDIM 4096

// ---------------- scratch (no cudaMalloc allowed) ----------------
__device__ float g_T[256 * 4096];            // 4 MB:  T[(i,n)][(j,m,c)]
__device__ float g_G[(size_t)4096 * 4096];   // 64 MB: G[row=(i,j,k)][col=(n,m,o)]

// ---------------- step 1: T[i,n,j,m,c] = sum_b core0[i,n,b] * core1[b,j,m,c] ----------
__global__ void build_T(const float* __restrict__ core0, const float* __restrict__ core1) {
    __shared__ float c0s[16];
    int in = blockIdx.x;                       // in = i*16 + n  (core0 flat [i][n][b])
    if (threadIdx.x < 16) c0s[threadIdx.x] = core0[in * 16 + threadIdx.x];
    __syncthreads();
    #pragma unroll
    for (int it = 0; it < 16; ++it) {
        int jmc = threadIdx.x + it * 256;      // j*256 + m*16 + c
        float s = 0.f;
        #pragma unroll
        for (int b = 0; b < 16; ++b) s += c0s[b] * core1[b * 4096 + jmc];
        g_T[in * 4096 + jmc] = s;
    }
}

// ---------------- step 2: G[(i,j,k),(n,m,o)] = sum_c T[i,n,j,m,c] * core2[c,k,o] ------
__global__ void build_G(const float* __restrict__ core2) {
    __shared__ float Ts[4096];   // [n][m][c] for fixed (i,j)
    __shared__ float C2[4096];   // [c][k][o]
    int ij = blockIdx.x; int i = ij >> 4, j = ij & 15;
    #pragma unroll
    for (int it = 0; it < 16; ++it) {
        int idx = threadIdx.x + it * 256;
        int n = idx >> 8, mc = idx & 255;
        Ts[idx] = g_T[(i * 16 + n) * 4096 + j * 256 + mc];
        C2[idx] = core2[idx];
    }
    __syncthreads();
    int m = threadIdx.x >> 4, o = threadIdx.x & 15;
    for (int k = 0; k < 16; ++k) {
        #pragma unroll
        for (int n = 0; n < 16; ++n) {
            float s = 0.f;
            #pragma unroll
            for (int c = 0; c < 16; ++c)
                s += Ts[n * 256 + m * 16 + c] * C2[c * 256 + k * 16 + o];
            g_G[(size_t)(i * 256 + j * 16 + k) * 4096 + n * 256 + m * 16 + o] = s;
        }
    }
}

// ---------------- step 3: GEMM  C[M,N] = A[M,K] * G[N,K]^T + bias, fp32 via bf16-split -
// Tile: BM=128, BN=128, BK=32. 8 warps (4x2), warp tile 32x64, mma m16n8k16 bf16.
// Split: a = ah + al (bf16), b = bh + bl; acc += ah*bh + ah*bl + al*bh  (fp32 accum).
#define BM 128
#define BN 128
#define BK 32
#define SSTR 36   // smem row stride in bf16 elements (padding kills bank conflicts)

__device__ __forceinline__ void mma16816(float* d, const uint32_t* a, uint32_t b0, uint32_t b1) {
    asm volatile(
        "mma.sync.aligned.m16n8k16.row.col.f32.bf16.bf16.f32 "
        "{%0,%1,%2,%3}, {%4,%5,%6,%7}, {%8,%9}, {%0,%1,%2,%3};\n"
        : "+f"(d[0]), "+f"(d[1]), "+f"(d[2]), "+f"(d[3])
        : "r"(a[0]), "r"(a[1]), "r"(a[2]), "r"(a[3]), "r"(b0), "r"(b1));
}

__device__ __forceinline__ uint32_t lds32(const __nv_bfloat16* p) {
    return *reinterpret_cast<const uint32_t*>(p);
}

__device__ __forceinline__ void split_store(__nv_bfloat16* hi, __nv_bfloat16* lo, float f) {
    __nv_bfloat16 h = __float2bfloat16(f);
    *hi = h;
    *lo = __float2bfloat16(f - __bfloat162float(h));
}

__global__ __launch_bounds__(256, 1)
void gemm_bf16split(const float* __restrict__ A, const float* __restrict__ bias,
                    float* __restrict__ C, int M) {
    __shared__ alignas(16) __nv_bfloat16 Ah[BM][SSTR], Al[BM][SSTR];
    __shared__ alignas(16) __nv_bfloat16 Bh[BN][SSTR], Bl[BN][SSTR];

    const int bm = blockIdx.y, bn = blockIdx.x;
    const int tid = threadIdx.x;
    const int warp = tid >> 5, lane = tid & 31;
    const int wm = warp & 3, wn = warp >> 2;       // warp grid 4(m) x 2(n)

    float acc[2][8][4];
    #pragma unroll
    for (int a = 0; a < 2; ++a)
        #pragma unroll
        for (int b = 0; b < 8; ++b)
            #pragma unroll
            for (int c = 0; c < 4; ++c) acc[a][b][c] = 0.f;

    for (int k0 = 0; k0 < KDIM; k0 += BK) {
        // ---- load + convert tiles (128x32 fp32 each) ----
        #pragma unroll
        for (int t = 0; t < 4; ++t) {
            int idx = tid + t * 256;               // float4 index, 1024 total
            int row = idx >> 3, c4 = (idx & 7) * 4;
            float4 va = *reinterpret_cast<const float4*>(
                &A[(size_t)(bm * BM + row) * KDIM + k0 + c4]);
            float4 vb = *reinterpret_cast<const float4*>(
                &g_G[(size_t)(bn * BN + row) * KDIM + k0 + c4]);
            split_store(&Ah[row][c4 + 0], &Al[row][c4 + 0], va.x);
            split_store(&Ah[row][c4 + 1], &Al[row][c4 + 1], va.y);
            split_store(&Ah[row][c4 + 2], &Al[row][c4 + 2], va.z);
            split_store(&Ah[row][c4 + 3], &Al[row][c4 + 3], va.w);
            split_store(&Bh[row][c4 + 0], &Bl[row][c4 + 0], vb.x);
            split_store(&Bh[row][c4 + 1], &Bl[row][c4 + 1], vb.y);
            split_store(&Bh[row][c4 + 2], &Bl[row][c4 + 2], vb.z);
            split_store(&Bh[row][c4 + 3], &Bl[row][c4 + 3], vb.w);
        }
        __syncthreads();

        // ---- compute: 2 k16 steps ----
        #pragma unroll
        for (int kk = 0; kk < BK; kk += 16) {
            uint32_t ah[2][4], al[2][4];
            const int kcol = kk + (lane & 3) * 2;
            #pragma unroll
            for (int im = 0; im < 2; ++im) {
                int r = wm * 32 + im * 16 + (lane >> 2);
                ah[im][0] = lds32(&Ah[r][kcol]);     ah[im][1] = lds32(&Ah[r + 8][kcol]);
                ah[im][2] = lds32(&Ah[r][kcol + 8]); ah[im][3] = lds32(&Ah[r + 8][kcol + 8]);
                al[im][0] = lds32(&Al[r][kcol]);     al[im][1] = lds32(&Al[r + 8][kcol]);
                al[im][2] = lds32(&Al[r][kcol + 8]); al[im][3] = lds32(&Al[r + 8][kcol + 8]);
            }
            #pragma unroll
            for (int jn = 0; jn < 8; ++jn) {
                int nr = wn * 64 + jn * 8 + (lane >> 2);
                uint32_t bh0 = lds32(&Bh[nr][kcol]), bh1 = lds32(&Bh[nr][kcol + 8]);
                uint32_t bl0 = lds32(&Bl[nr][kcol]), bl1 = lds32(&Bl[nr][kcol + 8]);
                #pragma unroll
                for (int im = 0; im < 2; ++im) {
                    mma16816(acc[im][jn], ah[im], bh0, bh1);
                    mma16816(acc[im][jn], ah[im], bl0, bl1);
                    mma16816(acc[im][jn], al[im], bh0, bh1);
                }
            }
        }
        __syncthreads();
    }

    // ---- epilogue: add bias, store fp32 ----
    #pragma unroll
    for (int im = 0; im < 2; ++im) {
        int r0 = bm * BM + wm * 32 + im * 16 + (lane >> 2);
        #pragma unroll
        for (int jn = 0; jn < 8; ++jn) {
            int cb = bn * BN + wn * 64 + jn * 8 + (lane & 3) * 2;
            float b0 = bias[cb], b1 = bias[cb + 1];
            C[(size_t)r0 * NDIM + cb]           = acc[im][jn][0] + b0;
            C[(size_t)r0 * NDIM + cb + 1]       = acc[im][jn][1] + b1;
            C[(size_t)(r0 + 8) * NDIM + cb]     = acc[im][jn][2] + b0;
            C[(size_t)(r0 + 8) * NDIM + cb + 1] = acc[im][jn][3] + b1;
        }
    }
}

// ---------------- launch ----------------
extern "C" void kernel_launch(void* const* d_in, const int* in_sizes, int n_in,
                              void* d_out, int out_size) {
    const float* x     = (const float*)d_in[0];
    const float* core0 = (const float*)d_in[1];
    const float* core1 = (const float*)d_in[2];
    const float* core2 = (const float*)d_in[3];
    const float* bias  = (const float*)d_in[4];
    float* out = (float*)d_out;

    int M = in_sizes[0] / KDIM;   // 8192

    build_T<<<256, 256>>>(core0, core1);
    build_G<<<256, 256>>>(core2);

    dim3 grid(NDIM / BN, M / BM);
    gemm_bf16split<<<grid, 256>>>(x, bias, out, M);
}

// round 4
// speedup vs baseline: 1.8247x; 1.8247x over previous
#include <cuda_runtime.h>
#include <cuda_bf16.h>
#include <cstdint>

#define KDIM 4096
#define NDIM 4096
#define MDIM 8192

// ---------------- scratch (no cudaMalloc allowed) ----------------
__device__ float g_T[256 * 4096];                         // 4 MB
__device__ __nv_bfloat16 g_Gh[(size_t)NDIM * KDIM];       // 32 MB
__device__ __nv_bfloat16 g_Gl[(size_t)NDIM * KDIM];       // 32 MB
__device__ __nv_bfloat16 g_xh[(size_t)MDIM * KDIM];       // 64 MB
__device__ __nv_bfloat16 g_xl[(size_t)MDIM * KDIM];       // 64 MB

// ---------------- step 1: T[i,n,j,m,c] = sum_b core0[i,n,b] * core1[b,j,m,c] ----------
__global__ void build_T(const float* __restrict__ core0, const float* __restrict__ core1) {
    __shared__ float c0s[16];
    int in = blockIdx.x;
    if (threadIdx.x < 16) c0s[threadIdx.x] = core0[in * 16 + threadIdx.x];
    __syncthreads();
    #pragma unroll
    for (int it = 0; it < 16; ++it) {
        int jmc = threadIdx.x + it * 256;
        float s = 0.f;
        #pragma unroll
        for (int b = 0; b < 16; ++b) s += c0s[b] * core1[b * 4096 + jmc];
        g_T[in * 4096 + jmc] = s;
    }
}

// ---------------- step 2: G hi/lo bf16 split of sum_c T * core2 ----------------------
__global__ void build_G(const float* __restrict__ core2) {
    __shared__ float Ts[4096];
    __shared__ float C2[4096];
    int ij = blockIdx.x; int i = ij >> 4, j = ij & 15;
    #pragma unroll
    for (int it = 0; it < 16; ++it) {
        int idx = threadIdx.x + it * 256;
        int n = idx >> 8, mc = idx & 255;
        Ts[idx] = g_T[(i * 16 + n) * 4096 + j * 256 + mc];
        C2[idx] = core2[idx];
    }
    __syncthreads();
    int m = threadIdx.x >> 4, o = threadIdx.x & 15;
    for (int k = 0; k < 16; ++k) {
        #pragma unroll
        for (int n = 0; n < 16; ++n) {
            float s = 0.f;
            #pragma unroll
            for (int c = 0; c < 16; ++c)
                s += Ts[n * 256 + m * 16 + c] * C2[c * 256 + k * 16 + o];
            size_t idx = (size_t)(i * 256 + j * 16 + k) * 4096 + n * 256 + m * 16 + o;
            __nv_bfloat16 h = __float2bfloat16(s);
            g_Gh[idx] = h;
            g_Gl[idx] = __float2bfloat16(s - __bfloat162float(h));
        }
    }
}

// ---------------- step 3: x -> bf16 hi/lo ----------------
__global__ void conv_x(const float* __restrict__ x) {
    size_t i = (size_t)blockIdx.x * blockDim.x + threadIdx.x;   // float4 index
    float4 v = reinterpret_cast<const float4*>(x)[i];
    __nv_bfloat16 h0 = __float2bfloat16(v.x), h1 = __float2bfloat16(v.y),
                  h2 = __float2bfloat16(v.z), h3 = __float2bfloat16(v.w);
    __nv_bfloat16 l0 = __float2bfloat16(v.x - __bfloat162float(h0));
    __nv_bfloat16 l1 = __float2bfloat16(v.y - __bfloat162float(h1));
    __nv_bfloat16 l2 = __float2bfloat16(v.z - __bfloat162float(h2));
    __nv_bfloat16 l3 = __float2bfloat16(v.w - __bfloat162float(h3));
    uint2 hp, lp;
    hp.x = (uint32_t)__bfloat16_as_ushort(h0) | ((uint32_t)__bfloat16_as_ushort(h1) << 16);
    hp.y = (uint32_t)__bfloat16_as_ushort(h2) | ((uint32_t)__bfloat16_as_ushort(h3) << 16);
    lp.x = (uint32_t)__bfloat16_as_ushort(l0) | ((uint32_t)__bfloat16_as_ushort(l1) << 16);
    lp.y = (uint32_t)__bfloat16_as_ushort(l2) | ((uint32_t)__bfloat16_as_ushort(l3) << 16);
    reinterpret_cast<uint2*>(g_xh)[i] = hp;
    reinterpret_cast<uint2*>(g_xl)[i] = lp;
}

// ---------------- step 4: pipelined mma.sync GEMM  C = x @ G^T + bias ----------------
#define BM 128
#define BN 256
#define BK 32
#define NCH (KDIM / BK)          // 128 chunks
#define NSTAGE 4
#define S_AH 0
#define S_AL 8192
#define S_BH 16384
#define S_BL 32768
#define STAGE_BYTES 49152        // Ah 8K + Al 8K + Bh 16K + Bl 16K
#define SMEM_BYTES (NSTAGE * STAGE_BYTES)   // 192 KB

// rows are 64 bytes (32 bf16); 4 chunks of 16B; XOR swizzle keeps ldmatrix/lds conflict-free
__device__ __forceinline__ uint32_t swz(int row, int byteInRow) {
    int c = byteInRow >> 4;
    int o = byteInRow & 15;
    return (uint32_t)(row * 64 + ((c ^ ((row >> 1) & 3)) << 4) + o);
}
__device__ __forceinline__ void cpa16(uint32_t d, const void* s) {
    asm volatile("cp.async.cg.shared.global [%0], [%1], 16;" :: "r"(d), "l"(s));
}
__device__ __forceinline__ uint32_t lds32(uint32_t addr) {
    uint32_t v;
    asm volatile("ld.shared.b32 %0, [%1];" : "=r"(v) : "r"(addr));
    return v;
}
__device__ __forceinline__ void ldmx4(uint32_t* r, uint32_t addr) {
    asm volatile("ldmatrix.sync.aligned.m8n8.x4.shared.b16 {%0,%1,%2,%3}, [%4];"
                 : "=r"(r[0]), "=r"(r[1]), "=r"(r[2]), "=r"(r[3]) : "r"(addr));
}
__device__ __forceinline__ void mma16816(float* d, const uint32_t* a, uint32_t b0, uint32_t b1) {
    asm volatile(
        "mma.sync.aligned.m16n8k16.row.col.f32.bf16.bf16.f32 "
        "{%0,%1,%2,%3}, {%4,%5,%6,%7}, {%8,%9}, {%0,%1,%2,%3};\n"
        : "+f"(d[0]), "+f"(d[1]), "+f"(d[2]), "+f"(d[3])
        : "r"(a[0]), "r"(a[1]), "r"(a[2]), "r"(a[3]), "r"(b0), "r"(b1));
}

__global__ __launch_bounds__(256, 1)
void gemm_pipe(const float* __restrict__ bias, float* __restrict__ C) {
    extern __shared__ char smraw[];
    const uint32_t sm0 = (uint32_t)__cvta_generic_to_shared(smraw);

    const int tid = threadIdx.x;
    const int warp = tid >> 5, lane = tid & 31;
    const int wm = warp >> 2, wn = warp & 3;      // 2 m-warps x 4 n-warps
    const int bn = blockIdx.x, bm = blockIdx.y;

    const __nv_bfloat16* Axh = g_xh + (size_t)bm * BM * KDIM;
    const __nv_bfloat16* Axl = g_xl + (size_t)bm * BM * KDIM;
    const __nv_bfloat16* Bgh = g_Gh + (size_t)bn * BN * KDIM;
    const __nv_bfloat16* Bgl = g_Gl + (size_t)bn * BN * KDIM;

    float acc[4][8][4];
    #pragma unroll
    for (int a = 0; a < 4; ++a)
        #pragma unroll
        for (int b = 0; b < 8; ++b)
            #pragma unroll
            for (int c = 0; c < 4; ++c) acc[a][b][c] = 0.f;

    auto loadStage = [&](int ch, int st) {
        const uint32_t sb = sm0 + (uint32_t)st * STAGE_BYTES;
        const int kc = ch * BK;
        #pragma unroll
        for (int t = 0; t < 2; ++t) {             // A: 512 chunks of 16B per half
            int q = tid + t * 256;
            int row = q >> 2, c = q & 3;
            uint32_t so = swz(row, c * 16);
            const char* ph = (const char*)(Axh + (size_t)row * KDIM + kc) + c * 16;
            const char* pl = (const char*)(Axl + (size_t)row * KDIM + kc) + c * 16;
            cpa16(sb + S_AH + so, ph);
            cpa16(sb + S_AL + so, pl);
        }
        #pragma unroll
        for (int t = 0; t < 4; ++t) {             // B: 1024 chunks of 16B per half
            int q = tid + t * 256;
            int row = q >> 2, c = q & 3;
            uint32_t so = swz(row, c * 16);
            const char* ph = (const char*)(Bgh + (size_t)row * KDIM + kc) + c * 16;
            const char* pl = (const char*)(Bgl + (size_t)row * KDIM + kc) + c * 16;
            cpa16(sb + S_BH + so, ph);
            cpa16(sb + S_BL + so, pl);
        }
    };

    // prologue: stages 0..2
    #pragma unroll
    for (int s = 0; s < NSTAGE - 1; ++s) {
        loadStage(s, s);
        asm volatile("cp.async.commit_group;");
    }

    for (int ch = 0; ch < NCH; ++ch) {
        asm volatile("cp.async.wait_group %0;" :: "n"(NSTAGE - 2));
        __syncthreads();
        if (ch + NSTAGE - 1 < NCH) loadStage(ch + NSTAGE - 1, (ch + NSTAGE - 1) & (NSTAGE - 1));
        asm volatile("cp.async.commit_group;");

        const uint32_t sb = sm0 + (uint32_t)(ch & (NSTAGE - 1)) * STAGE_BYTES;
        #pragma unroll
        for (int kk = 0; kk < BK; kk += 16) {
            uint32_t ah[4][4], al[4][4];
            #pragma unroll
            for (int im = 0; im < 4; ++im) {
                int row = wm * 64 + im * 16 + (lane & 15);
                int c = (kk >> 3) + (lane >> 4);
                uint32_t so = swz(row, c << 4);
                ldmx4(ah[im], sb + S_AH + so);
                ldmx4(al[im], sb + S_AL + so);
            }
            #pragma unroll
            for (int jn = 0; jn < 8; ++jn) {
                int nr = wn * 64 + jn * 8 + (lane >> 2);
                int kb = (kk + (lane & 3) * 2) * 2;
                uint32_t sh0 = swz(nr, kb), sh1 = swz(nr, kb + 16);
                uint32_t bh0 = lds32(sb + S_BH + sh0), bh1 = lds32(sb + S_BH + sh1);
                uint32_t bl0 = lds32(sb + S_BL + sh0), bl1 = lds32(sb + S_BL + sh1);
                #pragma unroll
                for (int im = 0; im < 4; ++im) {
                    mma16816(acc[im][jn], ah[im], bh0, bh1);
                    mma16816(acc[im][jn], ah[im], bl0, bl1);
                    mma16816(acc[im][jn], al[im], bh0, bh1);
                }
            }
        }
    }

    // ---- epilogue: add bias, store fp32 ----
    #pragma unroll
    for (int im = 0; im < 4; ++im) {
        int r0 = bm * BM + wm * 64 + im * 16 + (lane >> 2);
        #pragma unroll
        for (int jn = 0; jn < 8; ++jn) {
            int cb = bn * BN + wn * 64 + jn * 8 + (lane & 3) * 2;
            float b0 = bias[cb], b1 = bias[cb + 1];
            float2 v0, v1;
            v0.x = acc[im][jn][0] + b0; v0.y = acc[im][jn][1] + b1;
            v1.x = acc[im][jn][2] + b0; v1.y = acc[im][jn][3] + b1;
            *reinterpret_cast<float2*>(C + (size_t)r0 * NDIM + cb) = v0;
            *reinterpret_cast<float2*>(C + (size_t)(r0 + 8) * NDIM + cb) = v1;
        }
    }
}

// ---------------- launch ----------------
extern "C" void kernel_launch(void* const* d_in, const int* in_sizes, int n_in,
                              void* d_out, int out_size) {
    const float* x     = (const float*)d_in[0];
    const float* core0 = (const float*)d_in[1];
    const float* core1 = (const float*)d_in[2];
    const float* core2 = (const float*)d_in[3];
    const float* bias  = (const float*)d_in[4];
    float* out = (float*)d_out;

    build_T<<<256, 256>>>(core0, core1);
    build_G<<<256, 256>>>(core2);
    conv_x<<<(MDIM * KDIM / 4) / 256, 256>>>(x);

    cudaFuncSetAttribute(gemm_pipe, cudaFuncAttributeMaxDynamicSharedMemorySize, SMEM_BYTES);
    dim3 grid(NDIM / BN, MDIM / BM);     // (16, 64), x-fastest keeps G hot in L2
    gemm_pipe<<<grid, 256, SMEM_BYTES>>>(bias, out);
}

// round 5
// speedup vs baseline: 2.6077x; 1.4291x over previous
#include <cuda_runtime.h>
#include <cuda_bf16.h>
#include <cuda_fp16.h>
#include <cstdint>

#define KDIM 4096
#define NDIM 4096
#define MDIM 8192

// ---------------- scratch (no cudaMalloc allowed) ----------------
__device__ float g_T[256 * 4096];                    // 4 MB
__device__ __half g_Gf[(size_t)NDIM * KDIM];         // 32 MB (G rounded to fp16)
__device__ __half g_xh[(size_t)MDIM * KDIM];         // 64 MB (x hi)
__device__ __half g_xl[(size_t)MDIM * KDIM];         // 64 MB (x lo)

// ---------------- step 1: T[i,n,j,m,c] = sum_b core0[i,n,b] * core1[b,j,m,c] ----------
__global__ void build_T(const float* __restrict__ core0, const float* __restrict__ core1) {
    __shared__ float c0s[16];
    int in = blockIdx.x;
    if (threadIdx.x < 16) c0s[threadIdx.x] = core0[in * 16 + threadIdx.x];
    __syncthreads();
    #pragma unroll
    for (int it = 0; it < 16; ++it) {
        int jmc = threadIdx.x + it * 256;
        float s = 0.f;
        #pragma unroll
        for (int b = 0; b < 16; ++b) s += c0s[b] * core1[b * 4096 + jmc];
        g_T[in * 4096 + jmc] = s;
    }
}

// ---------------- step 2: G fp16 of sum_c T * core2 ----------------------
__global__ void build_G(const float* __restrict__ core2) {
    __shared__ float Ts[4096];
    __shared__ float C2[4096];
    int ij = blockIdx.x; int i = ij >> 4, j = ij & 15;
    #pragma unroll
    for (int it = 0; it < 16; ++it) {
        int idx = threadIdx.x + it * 256;
        int n = idx >> 8, mc = idx & 255;
        Ts[idx] = g_T[(i * 16 + n) * 4096 + j * 256 + mc];
        C2[idx] = core2[idx];
    }
    __syncthreads();
    int m = threadIdx.x >> 4, o = threadIdx.x & 15;
    for (int k = 0; k < 16; ++k) {
        #pragma unroll
        for (int n = 0; n < 16; ++n) {
            float s = 0.f;
            #pragma unroll
            for (int c = 0; c < 16; ++c)
                s += Ts[n * 256 + m * 16 + c] * C2[c * 256 + k * 16 + o];
            size_t idx = (size_t)(i * 256 + j * 16 + k) * 4096 + n * 256 + m * 16 + o;
            g_Gf[idx] = __float2half(s);
        }
    }
}

// ---------------- step 3: x -> fp16 hi/lo ----------------
__global__ void conv_x(const float* __restrict__ x) {
    size_t i = (size_t)blockIdx.x * blockDim.x + threadIdx.x;   // float4 index
    float4 v = reinterpret_cast<const float4*>(x)[i];
    __half h0 = __float2half(v.x), h1 = __float2half(v.y),
           h2 = __float2half(v.z), h3 = __float2half(v.w);
    __half l0 = __float2half(v.x - __half2float(h0));
    __half l1 = __float2half(v.y - __half2float(h1));
    __half l2 = __float2half(v.z - __half2float(h2));
    __half l3 = __float2half(v.w - __half2float(h3));
    uint2 hp, lp;
    hp.x = (uint32_t)__half_as_ushort(h0) | ((uint32_t)__half_as_ushort(h1) << 16);
    hp.y = (uint32_t)__half_as_ushort(h2) | ((uint32_t)__half_as_ushort(h3) << 16);
    lp.x = (uint32_t)__half_as_ushort(l0) | ((uint32_t)__half_as_ushort(l1) << 16);
    lp.y = (uint32_t)__half_as_ushort(l2) | ((uint32_t)__half_as_ushort(l3) << 16);
    reinterpret_cast<uint2*>(g_xh)[i] = hp;
    reinterpret_cast<uint2*>(g_xl)[i] = lp;
}

// ---------------- step 4: pipelined mma.sync GEMM  C = (xh+xl) @ Gf^T + bias ---------
#define BM 128
#define BN 256
#define BK 32
#define NCH (KDIM / BK)          // 128 chunks
#define NSTAGE 4
#define S_AH 0
#define S_AL 8192
#define S_B  16384
#define STAGE_BYTES 32768        // Ah 8K + Al 8K + B 16K
#define SMEM_BYTES (NSTAGE * STAGE_BYTES)   // 128 KB

// rows are 64 bytes (32 fp16); 4 chunks of 16B; XOR swizzle keeps ldmatrix/lds conflict-free
__device__ __forceinline__ uint32_t swz(int row, int byteInRow) {
    int c = byteInRow >> 4;
    int o = byteInRow & 15;
    return (uint32_t)(row * 64 + ((c ^ ((row >> 1) & 3)) << 4) + o);
}
__device__ __forceinline__ void cpa16(uint32_t d, const void* s) {
    asm volatile("cp.async.cg.shared.global [%0], [%1], 16;" :: "r"(d), "l"(s));
}
__device__ __forceinline__ uint32_t lds32(uint32_t addr) {
    uint32_t v;
    asm volatile("ld.shared.b32 %0, [%1];" : "=r"(v) : "r"(addr));
    return v;
}
__device__ __forceinline__ void ldmx4(uint32_t* r, uint32_t addr) {
    asm volatile("ldmatrix.sync.aligned.m8n8.x4.shared.b16 {%0,%1,%2,%3}, [%4];"
                 : "=r"(r[0]), "=r"(r[1]), "=r"(r[2]), "=r"(r[3]) : "r"(addr));
}
__device__ __forceinline__ void mma16816(float* d, const uint32_t* a, uint32_t b0, uint32_t b1) {
    asm volatile(
        "mma.sync.aligned.m16n8k16.row.col.f32.f16.f16.f32 "
        "{%0,%1,%2,%3}, {%4,%5,%6,%7}, {%8,%9}, {%0,%1,%2,%3};\n"
        : "+f"(d[0]), "+f"(d[1]), "+f"(d[2]), "+f"(d[3])
        : "r"(a[0]), "r"(a[1]), "r"(a[2]), "r"(a[3]), "r"(b0), "r"(b1));
}

__global__ __launch_bounds__(512, 1)
void gemm_pipe(const float* __restrict__ bias, float* __restrict__ C) {
    extern __shared__ char smraw[];
    const uint32_t sm0 = (uint32_t)__cvta_generic_to_shared(smraw);

    const int tid = threadIdx.x;
    const int warp = tid >> 5, lane = tid & 31;
    const int wm = warp >> 2, wn = warp & 3;      // 4 m-warps x 4 n-warps
    const int bn = blockIdx.x, bm = blockIdx.y;

    const __half* Axh = g_xh + (size_t)bm * BM * KDIM;
    const __half* Axl = g_xl + (size_t)bm * BM * KDIM;
    const __half* Bg  = g_Gf + (size_t)bn * BN * KDIM;

    float acc[2][8][4];
    #pragma unroll
    for (int a = 0; a < 2; ++a)
        #pragma unroll
        for (int b = 0; b < 8; ++b)
            #pragma unroll
            for (int c = 0; c < 4; ++c) acc[a][b][c] = 0.f;

    auto loadStage = [&](int ch, int st) {
        const uint32_t sb = sm0 + (uint32_t)st * STAGE_BYTES;
        const int kc = ch * BK;
        {   // A: 512 x 16B chunks per half, one per thread
            int row = tid >> 2, c = tid & 3;
            uint32_t so = swz(row, c * 16);
            cpa16(sb + S_AH + so, (const char*)(Axh + (size_t)row * KDIM + kc) + c * 16);
            cpa16(sb + S_AL + so, (const char*)(Axl + (size_t)row * KDIM + kc) + c * 16);
        }
        #pragma unroll
        for (int t = 0; t < 2; ++t) {             // B: 1024 x 16B chunks
            int q = tid + t * 512;
            int row = q >> 2, c = q & 3;
            uint32_t so = swz(row, c * 16);
            cpa16(sb + S_B + so, (const char*)(Bg + (size_t)row * KDIM + kc) + c * 16);
        }
    };

    // prologue: stages 0..2
    #pragma unroll
    for (int s = 0; s < NSTAGE - 1; ++s) {
        loadStage(s, s);
        asm volatile("cp.async.commit_group;");
    }

    for (int ch = 0; ch < NCH; ++ch) {
        asm volatile("cp.async.wait_group %0;" :: "n"(NSTAGE - 2));
        __syncthreads();
        if (ch + NSTAGE - 1 < NCH) loadStage(ch + NSTAGE - 1, (ch + NSTAGE - 1) & (NSTAGE - 1));
        asm volatile("cp.async.commit_group;");

        const uint32_t sb = sm0 + (uint32_t)(ch & (NSTAGE - 1)) * STAGE_BYTES;
        #pragma unroll
        for (int kk = 0; kk < BK; kk += 16) {
            uint32_t ah[2][4], al[2][4];
            #pragma unroll
            for (int im = 0; im < 2; ++im) {
                int row = wm * 32 + im * 16 + (lane & 15);
                int c = (kk >> 3) + (lane >> 4);
                uint32_t so = swz(row, c << 4);
                ldmx4(ah[im], sb + S_AH + so);
                ldmx4(al[im], sb + S_AL + so);
            }
            #pragma unroll
            for (int jn = 0; jn < 8; ++jn) {
                int nr = wn * 64 + jn * 8 + (lane >> 2);
                int kb = (kk + (lane & 3) * 2) * 2;
                uint32_t b0 = lds32(sb + S_B + swz(nr, kb));
                uint32_t b1 = lds32(sb + S_B + swz(nr, kb + 16));
                #pragma unroll
                for (int im = 0; im < 2; ++im) {
                    mma16816(acc[im][jn], ah[im], b0, b1);
                    mma16816(acc[im][jn], al[im], b0, b1);
                }
            }
        }
    }

    // ---- epilogue: add bias, store fp32 ----
    #pragma unroll
    for (int im = 0; im < 2; ++im) {
        int r0 = bm * BM + wm * 32 + im * 16 + (lane >> 2);
        #pragma unroll
        for (int jn = 0; jn < 8; ++jn) {
            int cb = bn * BN + wn * 64 + jn * 8 + (lane & 3) * 2;
            float b0 = bias[cb], b1 = bias[cb + 1];
            float2 v0, v1;
            v0.x = acc[im][jn][0] + b0; v0.y = acc[im][jn][1] + b1;
            v1.x = acc[im][jn][2] + b0; v1.y = acc[im][jn][3] + b1;
            *reinterpret_cast<float2*>(C + (size_t)r0 * NDIM + cb) = v0;
            *reinterpret_cast<float2*>(C + (size_t)(r0 + 8) * NDIM + cb) = v1;
        }
    }
}

// ---------------- launch ----------------
extern "C" void kernel_launch(void* const* d_in, const int* in_sizes, int n_in,
                              void* d_out, int out_size) {
    const float* x     = (const float*)d_in[0];
    const float* core0 = (const float*)d_in[1];
    const float* core1 = (const float*)d_in[2];
    const float* core2 = (const float*)d_in[3];
    const float* bias  = (const float*)d_in[4];
    float* out = (float*)d_out;

    build_T<<<256, 256>>>(core0, core1);
    build_G<<<256, 256>>>(core2);
    conv_x<<<(MDIM * KDIM / 4) / 256, 256>>>(x);

    cudaFuncSetAttribute(gemm_pipe, cudaFuncAttributeMaxDynamicSharedMemorySize, SMEM_BYTES);
    dim3 grid(NDIM / BN, MDIM / BM);     // (16, 64), x-fastest keeps G hot in L2
    gemm_pipe<<<grid, 512, SMEM_BYTES>>>(bias, out);
}

// round 6
// speedup vs baseline: 4.9778x; 1.9089x over previous
#include <cuda_runtime.h>
#include <cuda_fp16.h>
#include <cstdint>

#define KDIM 4096
#define NDIM 4096
#define MDIM 8192

// ---------------- scratch (no cudaMalloc allowed) ----------------
__device__ float g_T[256 * 4096];                    // 4 MB
__device__ __half g_Gf[(size_t)NDIM * KDIM];         // 32 MB (G rounded to fp16)
__device__ __half g_xf[(size_t)MDIM * KDIM];         // 64 MB (x rounded to fp16)

// ---------------- step 1: T[i,n,j,m,c] = sum_b core0[i,n,b] * core1[b,j,m,c] ----------
__global__ void build_T(const float* __restrict__ core0, const float* __restrict__ core1) {
    __shared__ float c0s[16];
    int in = blockIdx.x;
    if (threadIdx.x < 16) c0s[threadIdx.x] = core0[in * 16 + threadIdx.x];
    __syncthreads();
    #pragma unroll
    for (int it = 0; it < 16; ++it) {
        int jmc = threadIdx.x + it * 256;
        float s = 0.f;
        #pragma unroll
        for (int b = 0; b < 16; ++b) s += c0s[b] * core1[b * 4096 + jmc];
        g_T[in * 4096 + jmc] = s;
    }
}

// ---------------- step 2: G fp16 of sum_c T * core2 ----------------------
__global__ void build_G(const float* __restrict__ core2) {
    __shared__ float Ts[4096];
    __shared__ float C2[4096];
    int ij = blockIdx.x; int i = ij >> 4, j = ij & 15;
    #pragma unroll
    for (int it = 0; it < 16; ++it) {
        int idx = threadIdx.x + it * 256;
        int n = idx >> 8, mc = idx & 255;
        Ts[idx] = g_T[(i * 16 + n) * 4096 + j * 256 + mc];
        C2[idx] = core2[idx];
    }
    __syncthreads();
    int m = threadIdx.x >> 4, o = threadIdx.x & 15;
    for (int k = 0; k < 16; ++k) {
        #pragma unroll
        for (int n = 0; n < 16; ++n) {
            float s = 0.f;
            #pragma unroll
            for (int c = 0; c < 16; ++c)
                s += Ts[n * 256 + m * 16 + c] * C2[c * 256 + k * 16 + o];
            size_t idx = (size_t)(i * 256 + j * 16 + k) * 4096 + n * 256 + m * 16 + o;
            g_Gf[idx] = __float2half(s);
        }
    }
}

// ---------------- step 3: x -> fp16 ----------------
__global__ void conv_x(const float* __restrict__ x) {
    size_t i = (size_t)blockIdx.x * blockDim.x + threadIdx.x;   // float4 index
    float4 v = reinterpret_cast<const float4*>(x)[i];
    uint2 hp;
    hp.x = (uint32_t)__half_as_ushort(__float2half(v.x)) |
           ((uint32_t)__half_as_ushort(__float2half(v.y)) << 16);
    hp.y = (uint32_t)__half_as_ushort(__float2half(v.z)) |
           ((uint32_t)__half_as_ushort(__float2half(v.w)) << 16);
    reinterpret_cast<uint2*>(g_xf)[i] = hp;
}

// ---------------- step 4: pipelined mma.sync GEMM  C = x @ G^T + bias (1 pass fp16) ---
#define BM 128
#define BN 256
#define BK 64
#define NCH (KDIM / BK)          // 64 chunks
#define NSTAGE 4
#define S_A 0
#define S_B 16384
#define STAGE_BYTES 49152        // A 16K + B 32K
#define SMEM_BYTES (NSTAGE * STAGE_BYTES)   // 192 KB

// rows are 128 bytes (64 fp16); 8 chunks of 16B; XOR swizzle => conflict-free ldmatrix
__device__ __forceinline__ uint32_t swz(int row, int byteInRow) {
    int c = byteInRow >> 4;
    int o = byteInRow & 15;
    return (uint32_t)(row * 128 + (((c ^ row) & 7) << 4) + o);
}
__device__ __forceinline__ void cpa16(uint32_t d, const void* s) {
    asm volatile("cp.async.cg.shared.global [%0], [%1], 16;" :: "r"(d), "l"(s));
}
__device__ __forceinline__ void ldmx4(uint32_t* r, uint32_t addr) {
    asm volatile("ldmatrix.sync.aligned.m8n8.x4.shared.b16 {%0,%1,%2,%3}, [%4];"
                 : "=r"(r[0]), "=r"(r[1]), "=r"(r[2]), "=r"(r[3]) : "r"(addr));
}
__device__ __forceinline__ void mma16816(float* d, const uint32_t* a, uint32_t b0, uint32_t b1) {
    asm volatile(
        "mma.sync.aligned.m16n8k16.row.col.f32.f16.f16.f32 "
        "{%0,%1,%2,%3}, {%4,%5,%6,%7}, {%8,%9}, {%0,%1,%2,%3};\n"
        : "+f"(d[0]), "+f"(d[1]), "+f"(d[2]), "+f"(d[3])
        : "r"(a[0]), "r"(a[1]), "r"(a[2]), "r"(a[3]), "r"(b0), "r"(b1));
}

__global__ __launch_bounds__(512, 1)
void gemm_pipe(const float* __restrict__ bias, float* __restrict__ C) {
    extern __shared__ char smraw[];
    const uint32_t sm0 = (uint32_t)__cvta_generic_to_shared(smraw);

    const int tid = threadIdx.x;
    const int warp = tid >> 5, lane = tid & 31;
    const int wm = warp >> 2, wn = warp & 3;      // 4 m-warps x 4 n-warps
    const int bn = blockIdx.x, bm = blockIdx.y;

    const __half* Ax = g_xf + (size_t)bm * BM * KDIM;
    const __half* Bg = g_Gf + (size_t)bn * BN * KDIM;

    float acc[2][8][4];
    #pragma unroll
    for (int a = 0; a < 2; ++a)
        #pragma unroll
        for (int b = 0; b < 8; ++b)
            #pragma unroll
            for (int c = 0; c < 4; ++c) acc[a][b][c] = 0.f;

    auto loadStage = [&](int ch, int st) {
        const uint32_t sb = sm0 + (uint32_t)st * STAGE_BYTES;
        const int kc = ch * BK;
        #pragma unroll
        for (int t = 0; t < 2; ++t) {             // A: 1024 x 16B chunks
            int q = tid + t * 512;
            int row = q >> 3, c = q & 7;
            cpa16(sb + S_A + swz(row, c * 16),
                  (const char*)(Ax + (size_t)row * KDIM + kc) + c * 16);
        }
        #pragma unroll
        for (int t = 0; t < 4; ++t) {             // B: 2048 x 16B chunks
            int q = tid + t * 512;
            int row = q >> 3, c = q & 7;
            cpa16(sb + S_B + swz(row, c * 16),
                  (const char*)(Bg + (size_t)row * KDIM + kc) + c * 16);
        }
    };

    // prologue: stages 0..2
    #pragma unroll
    for (int s = 0; s < NSTAGE - 1; ++s) {
        loadStage(s, s);
        asm volatile("cp.async.commit_group;");
    }

    for (int ch = 0; ch < NCH; ++ch) {
        asm volatile("cp.async.wait_group %0;" :: "n"(NSTAGE - 2));
        __syncthreads();
        if (ch + NSTAGE - 1 < NCH) loadStage(ch + NSTAGE - 1, (ch + NSTAGE - 1) & (NSTAGE - 1));
        asm volatile("cp.async.commit_group;");

        const uint32_t sb = sm0 + (uint32_t)(ch & (NSTAGE - 1)) * STAGE_BYTES;
        #pragma unroll
        for (int kk = 0; kk < BK; kk += 16) {
            uint32_t av[2][4];
            #pragma unroll
            for (int im = 0; im < 2; ++im) {
                int row = wm * 32 + im * 16 + (lane & 15);
                int byte = kk * 2 + ((lane >> 4) << 4);
                ldmx4(av[im], sb + S_A + swz(row, byte));
            }
            #pragma unroll
            for (int jp = 0; jp < 4; ++jp) {      // each ldmatrix.x4 covers 2 jn octets
                int nrow = wn * 64 + (jp * 2 + (lane >> 4)) * 8 + (lane & 7);
                int byte = kk * 2 + (((lane >> 3) & 1) << 4);
                uint32_t bv[4];
                ldmx4(bv, sb + S_B + swz(nrow, byte));
                #pragma unroll
                for (int im = 0; im < 2; ++im) {
                    mma16816(acc[im][jp * 2],     av[im], bv[0], bv[1]);
                    mma16816(acc[im][jp * 2 + 1], av[im], bv[2], bv[3]);
                }
            }
        }
    }

    // ---- epilogue: add bias, store fp32 ----
    #pragma unroll
    for (int im = 0; im < 2; ++im) {
        int r0 = bm * BM + wm * 32 + im * 16 + (lane >> 2);
        #pragma unroll
        for (int jn = 0; jn < 8; ++jn) {
            int cb = bn * BN + wn * 64 + jn * 8 + (lane & 3) * 2;
            float b0 = bias[cb], b1 = bias[cb + 1];
            float2 v0, v1;
            v0.x = acc[im][jn][0] + b0; v0.y = acc[im][jn][1] + b1;
            v1.x = acc[im][jn][2] + b0; v1.y = acc[im][jn][3] + b1;
            *reinterpret_cast<float2*>(C + (size_t)r0 * NDIM + cb) = v0;
            *reinterpret_cast<float2*>(C + (size_t)(r0 + 8) * NDIM + cb) = v1;
        }
    }
}

// ---------------- launch ----------------
extern "C" void kernel_launch(void* const* d_in, const int* in_sizes, int n_in,
                              void* d_out, int out_size) {
    const float* x     = (const float*)d_in[0];
    const float* core0 = (const float*)d_in[1];
    const float* core1 = (const float*)d_in[2];
    const float* core2 = (const float*)d_in[3];
    const float* bias  = (const float*)d_in[4];
    float* out = (float*)d_out;

    build_T<<<256, 256>>>(core0, core1);
    build_G<<<256, 256>>>(core2);
    conv_x<<<(MDIM * KDIM / 4) / 256, 256>>>(x);

    cudaFuncSetAttribute(gemm_pipe, cudaFuncAttributeMaxDynamicSharedMemorySize, SMEM_BYTES);
    dim3 grid(NDIM / BN, MDIM / BM);     // (16, 64), x-fastest keeps G hot in L2
    gemm_pipe<<<grid, 512, SMEM_BYTES>>>(bias, out);
}

// round 7
// speedup vs baseline: 5.5147x; 1.1079x over previous
#include <cuda_runtime.h>
#include <cuda_fp16.h>
#include <cstdint>

#define KDIM 4096
#define NDIM 4096
#define MDIM 8192

// ---------------- scratch (no cudaMalloc allowed) ----------------
__device__ float g_T[256 * 4096];                    // 4 MB
__device__ __half g_Gf[(size_t)NDIM * KDIM];         // 32 MB (G rounded to fp16)
__device__ __half g_xf[(size_t)MDIM * KDIM];         // 64 MB (x rounded to fp16)

// ---------------- step 1: T[i,n,j,m,c] = sum_b core0[i,n,b] * core1[b,j,m,c] ----------
__global__ void build_T(const float* __restrict__ core0, const float* __restrict__ core1) {
    __shared__ float c0s[16];
    int in = blockIdx.x;                 // 256
    int quarter = blockIdx.y;            // 4
    if (threadIdx.x < 16) c0s[threadIdx.x] = core0[in * 16 + threadIdx.x];
    __syncthreads();
    #pragma unroll
    for (int it = 0; it < 4; ++it) {
        int jmc = quarter * 1024 + threadIdx.x + it * 256;
        float s = 0.f;
        #pragma unroll
        for (int b = 0; b < 16; ++b) s += c0s[b] * core1[b * 4096 + jmc];
        g_T[in * 4096 + jmc] = s;
    }
}

// ---------------- step 2: G fp16 of sum_c T * core2 ----------------------
__global__ void build_G(const float* __restrict__ core2) {
    __shared__ float Ts[4096];
    __shared__ float C2[4096];
    int ij = blockIdx.x; int i = ij >> 4, j = ij & 15;
    #pragma unroll
    for (int it = 0; it < 16; ++it) {
        int idx = threadIdx.x + it * 256;
        int n = idx >> 8, mc = idx & 255;
        Ts[idx] = g_T[(i * 16 + n) * 4096 + j * 256 + mc];
        C2[idx] = core2[idx];
    }
    __syncthreads();
    int m = threadIdx.x >> 4, o = threadIdx.x & 15;
    for (int k = 0; k < 16; ++k) {
        #pragma unroll
        for (int n = 0; n < 16; ++n) {
            float s = 0.f;
            #pragma unroll
            for (int c = 0; c < 16; ++c)
                s += Ts[n * 256 + m * 16 + c] * C2[c * 256 + k * 16 + o];
            size_t idx = (size_t)(i * 256 + j * 16 + k) * 4096 + n * 256 + m * 16 + o;
            g_Gf[idx] = __float2half(s);
        }
    }
}

// ---------------- step 3: x -> fp16 ----------------
__global__ void conv_x(const float* __restrict__ x) {
    size_t i = (size_t)blockIdx.x * blockDim.x + threadIdx.x;   // float4 index
    float4 v = reinterpret_cast<const float4*>(x)[i];
    uint2 hp;
    hp.x = (uint32_t)__half_as_ushort(__float2half(v.x)) |
           ((uint32_t)__half_as_ushort(__float2half(v.y)) << 16);
    hp.y = (uint32_t)__half_as_ushort(__float2half(v.z)) |
           ((uint32_t)__half_as_ushort(__float2half(v.w)) << 16);
    reinterpret_cast<uint2*>(g_xf)[i] = hp;
}

// ---------------- step 4: pipelined mma.sync GEMM, 2 CTAs/SM ----------------
#define BM 128
#define BN 128
#define BK 64
#define NCH (KDIM / BK)          // 64 chunks
#define NSTAGE 3
#define S_A 0
#define S_B 16384
#define STAGE_BYTES 32768        // A 16K + B 16K
#define SMEM_BYTES (NSTAGE * STAGE_BYTES)   // 96 KB -> 2 CTAs/SM

// rows are 128 bytes (64 fp16); 8 chunks of 16B; XOR swizzle => conflict-free ldmatrix
__device__ __forceinline__ uint32_t swz(int row, int byteInRow) {
    int c = byteInRow >> 4;
    int o = byteInRow & 15;
    return (uint32_t)(row * 128 + (((c ^ row) & 7) << 4) + o);
}
__device__ __forceinline__ void cpa16(uint32_t d, const void* s) {
    asm volatile("cp.async.cg.shared.global [%0], [%1], 16;" :: "r"(d), "l"(s));
}
__device__ __forceinline__ void ldmx4(uint32_t* r, uint32_t addr) {
    asm volatile("ldmatrix.sync.aligned.m8n8.x4.shared.b16 {%0,%1,%2,%3}, [%4];"
                 : "=r"(r[0]), "=r"(r[1]), "=r"(r[2]), "=r"(r[3]) : "r"(addr));
}
__device__ __forceinline__ void mma16816(float* d, const uint32_t* a, uint32_t b0, uint32_t b1) {
    asm volatile(
        "mma.sync.aligned.m16n8k16.row.col.f32.f16.f16.f32 "
        "{%0,%1,%2,%3}, {%4,%5,%6,%7}, {%8,%9}, {%0,%1,%2,%3};\n"
        : "+f"(d[0]), "+f"(d[1]), "+f"(d[2]), "+f"(d[3])
        : "r"(a[0]), "r"(a[1]), "r"(a[2]), "r"(a[3]), "r"(b0), "r"(b1));
}

__global__ __launch_bounds__(256, 2)
void gemm_pipe(const float* __restrict__ bias, float* __restrict__ C) {
    extern __shared__ char smraw[];
    const uint32_t sm0 = (uint32_t)__cvta_generic_to_shared(smraw);

    const int tid = threadIdx.x;
    const int warp = tid >> 5, lane = tid & 31;
    const int wm = warp >> 2, wn = warp & 3;      // 2 m-warps x 4 n-warps
    const int bn = blockIdx.x, bm = blockIdx.y;

    const __half* Ax = g_xf + (size_t)bm * BM * KDIM;
    const __half* Bg = g_Gf + (size_t)bn * BN * KDIM;

    float acc[4][4][4];
    #pragma unroll
    for (int a = 0; a < 4; ++a)
        #pragma unroll
        for (int b = 0; b < 4; ++b)
            #pragma unroll
            for (int c = 0; c < 4; ++c) acc[a][b][c] = 0.f;

    auto loadStage = [&](int ch, int st) {
        const uint32_t sb = sm0 + (uint32_t)st * STAGE_BYTES;
        const int kc = ch * BK;
        #pragma unroll
        for (int t = 0; t < 4; ++t) {             // A: 1024 x 16B chunks
            int q = tid + t * 256;
            int row = q >> 3, c = q & 7;
            cpa16(sb + S_A + swz(row, c * 16),
                  (const char*)(Ax + (size_t)row * KDIM + kc) + c * 16);
        }
        #pragma unroll
        for (int t = 0; t < 4; ++t) {             // B: 1024 x 16B chunks
            int q = tid + t * 256;
            int row = q >> 3, c = q & 7;
            cpa16(sb + S_B + swz(row, c * 16),
                  (const char*)(Bg + (size_t)row * KDIM + kc) + c * 16);
        }
    };

    // prologue: stages 0,1
    loadStage(0, 0);
    asm volatile("cp.async.commit_group;");
    loadStage(1, 1);
    asm volatile("cp.async.commit_group;");

    int cur = 0, nxt = 2;
    for (int ch = 0; ch < NCH; ++ch) {
        asm volatile("cp.async.wait_group 1;");
        __syncthreads();
        if (ch + 2 < NCH) loadStage(ch + 2, nxt);
        asm volatile("cp.async.commit_group;");

        const uint32_t sb = sm0 + (uint32_t)cur * STAGE_BYTES;
        cur = (cur == 2) ? 0 : cur + 1;
        nxt = (nxt == 2) ? 0 : nxt + 1;

        #pragma unroll
        for (int kk = 0; kk < BK; kk += 16) {
            uint32_t av[4][4];
            #pragma unroll
            for (int im = 0; im < 4; ++im) {
                int row = wm * 64 + im * 16 + (lane & 15);
                int byte = kk * 2 + ((lane >> 4) << 4);
                ldmx4(av[im], sb + S_A + swz(row, byte));
            }
            #pragma unroll
            for (int jp = 0; jp < 2; ++jp) {      // each ldmatrix.x4 covers 2 jn octets
                int nrow = wn * 32 + (jp * 2 + (lane >> 4)) * 8 + (lane & 7);
                int byte = kk * 2 + (((lane >> 3) & 1) << 4);
                uint32_t bv[4];
                ldmx4(bv, sb + S_B + swz(nrow, byte));
                #pragma unroll
                for (int im = 0; im < 4; ++im) {
                    mma16816(acc[im][jp * 2],     av[im], bv[0], bv[1]);
                    mma16816(acc[im][jp * 2 + 1], av[im], bv[2], bv[3]);
                }
            }
        }
    }

    // ---- epilogue: add bias, store fp32 ----
    #pragma unroll
    for (int im = 0; im < 4; ++im) {
        int r0 = bm * BM + wm * 64 + im * 16 + (lane >> 2);
        #pragma unroll
        for (int jn = 0; jn < 4; ++jn) {
            int cb = bn * BN + wn * 32 + jn * 8 + (lane & 3) * 2;
            float b0 = bias[cb], b1 = bias[cb + 1];
            float2 v0, v1;
            v0.x = acc[im][jn][0] + b0; v0.y = acc[im][jn][1] + b1;
            v1.x = acc[im][jn][2] + b0; v1.y = acc[im][jn][3] + b1;
            *reinterpret_cast<float2*>(C + (size_t)r0 * NDIM + cb) = v0;
            *reinterpret_cast<float2*>(C + (size_t)(r0 + 8) * NDIM + cb) = v1;
        }
    }
}

// ---------------- launch ----------------
extern "C" void kernel_launch(void* const* d_in, const int* in_sizes, int n_in,
                              void* d_out, int out_size) {
    const float* x     = (const float*)d_in[0];
    const float* core0 = (const float*)d_in[1];
    const float* core1 = (const float*)d_in[2];
    const float* core2 = (const float*)d_in[3];
    const float* bias  = (const float*)d_in[4];
    float* out = (float*)d_out;

    build_T<<<dim3(256, 4), 256>>>(core0, core1);
    build_G<<<256, 256>>>(core2);
    conv_x<<<(MDIM * KDIM / 4) / 256, 256>>>(x);

    cudaFuncSetAttribute(gemm_pipe, cudaFuncAttributeMaxDynamicSharedMemorySize, SMEM_BYTES);
    dim3 grid(NDIM / BN, MDIM / BM);     // (32, 64), x-fastest keeps G hot in L2
    gemm_pipe<<<grid, 256, SMEM_BYTES>>>(bias, out);
}

// round 8
// speedup vs baseline: 5.5748x; 1.0109x over previous
#include <cuda_runtime.h>
#include <cuda_fp16.h>
#include <cstdint>

#define KDIM 4096
#define NDIM 4096
#define MDIM 8192

// ---------------- scratch (no cudaMalloc allowed) ----------------
__device__ float g_T[256 * 4096];                    // 4 MB
__device__ __half g_Gf[(size_t)NDIM * KDIM];         // 32 MB (G rounded to fp16)
__device__ __half g_xf[(size_t)MDIM * KDIM];         // 64 MB (x rounded to fp16)

// ---------------- step 1: T[i,n,j,m,c] = sum_b core0[i,n,b] * core1[b,j,m,c] ----------
__global__ void build_T(const float* __restrict__ core0, const float* __restrict__ core1) {
    __shared__ float c0s[16];
    int in = blockIdx.x;                 // 256
    int quarter = blockIdx.y;            // 4
    if (threadIdx.x < 16) c0s[threadIdx.x] = core0[in * 16 + threadIdx.x];
    __syncthreads();
    #pragma unroll
    for (int it = 0; it < 4; ++it) {
        int jmc = quarter * 1024 + threadIdx.x + it * 256;
        float s = 0.f;
        #pragma unroll
        for (int b = 0; b < 16; ++b) s += c0s[b] * core1[b * 4096 + jmc];
        g_T[in * 4096 + jmc] = s;
    }
}

// ---------------- step 2: G fp16 of sum_c T * core2 (k-split, c2 in regs) ------------
__global__ void build_G(const float* __restrict__ core2) {
    __shared__ float Ts[4096];
    __shared__ float C2[4096];
    int ij = blockIdx.x; int i = ij >> 4, j = ij & 15;
    int k0 = blockIdx.y * 8;
    #pragma unroll
    for (int it = 0; it < 16; ++it) {
        int idx = threadIdx.x + it * 256;
        int n = idx >> 8, mc = idx & 255;
        Ts[idx] = g_T[(i * 16 + n) * 4096 + j * 256 + mc];
        C2[idx] = core2[idx];
    }
    __syncthreads();
    int m = threadIdx.x >> 4, o = threadIdx.x & 15;
    for (int k = k0; k < k0 + 8; ++k) {
        float c2r[16];
        #pragma unroll
        for (int c = 0; c < 16; ++c) c2r[c] = C2[c * 256 + k * 16 + o];
        #pragma unroll
        for (int n = 0; n < 16; ++n) {
            float s = 0.f;
            #pragma unroll
            for (int c = 0; c < 16; ++c)
                s += Ts[n * 256 + m * 16 + c] * c2r[c];
            size_t idx = (size_t)(i * 256 + j * 16 + k) * 4096 + n * 256 + m * 16 + o;
            g_Gf[idx] = __float2half(s);
        }
    }
}

// ---------------- step 3: x -> fp16 ----------------
__global__ void conv_x(const float* __restrict__ x) {
    size_t i = (size_t)blockIdx.x * blockDim.x + threadIdx.x;   // float4 index
    float4 v = reinterpret_cast<const float4*>(x)[i];
    uint2 hp;
    hp.x = (uint32_t)__half_as_ushort(__float2half(v.x)) |
           ((uint32_t)__half_as_ushort(__float2half(v.y)) << 16);
    hp.y = (uint32_t)__half_as_ushort(__float2half(v.z)) |
           ((uint32_t)__half_as_ushort(__float2half(v.w)) << 16);
    reinterpret_cast<uint2*>(g_xf)[i] = hp;
}

// ---------------- step 4: GEMM, 128-thread CTAs, warp tile 64x64, 2 CTAs/SM ----------
#define BM 128
#define BN 128
#define BK 64
#define NCH (KDIM / BK)          // 64 chunks
#define NSTAGE 3
#define S_A 0
#define S_B 16384
#define STAGE_BYTES 32768        // A 16K + B 16K
#define SMEM_BYTES (NSTAGE * STAGE_BYTES)   // 96 KB -> 2 CTAs/SM

// rows are 128 bytes (64 fp16); 8 chunks of 16B; XOR swizzle => conflict-free ldmatrix
__device__ __forceinline__ uint32_t swz(int row, int byteInRow) {
    int c = byteInRow >> 4;
    int o = byteInRow & 15;
    return (uint32_t)(row * 128 + (((c ^ row) & 7) << 4) + o);
}
__device__ __forceinline__ void cpa16(uint32_t d, const void* s) {
    asm volatile("cp.async.cg.shared.global [%0], [%1], 16;" :: "r"(d), "l"(s));
}
__device__ __forceinline__ void ldmx4(uint32_t* r, uint32_t addr) {
    asm volatile("ldmatrix.sync.aligned.m8n8.x4.shared.b16 {%0,%1,%2,%3}, [%4];"
                 : "=r"(r[0]), "=r"(r[1]), "=r"(r[2]), "=r"(r[3]) : "r"(addr));
}
__device__ __forceinline__ void mma16816(float* d, const uint32_t* a, uint32_t b0, uint32_t b1) {
    asm volatile(
        "mma.sync.aligned.m16n8k16.row.col.f32.f16.f16.f32 "
        "{%0,%1,%2,%3}, {%4,%5,%6,%7}, {%8,%9}, {%0,%1,%2,%3};\n"
        : "+f"(d[0]), "+f"(d[1]), "+f"(d[2]), "+f"(d[3])
        : "r"(a[0]), "r"(a[1]), "r"(a[2]), "r"(a[3]), "r"(b0), "r"(b1));
}

__global__ __launch_bounds__(128, 2)
void gemm_pipe(const float* __restrict__ bias, float* __restrict__ C) {
    extern __shared__ char smraw[];
    const uint32_t sm0 = (uint32_t)__cvta_generic_to_shared(smraw);

    const int tid = threadIdx.x;
    const int warp = tid >> 5, lane = tid & 31;
    const int wm = warp >> 1, wn = warp & 1;      // 2 m-warps x 2 n-warps, 64x64 each
    const int bn = blockIdx.x, bm = blockIdx.y;

    const __half* Ax = g_xf + (size_t)bm * BM * KDIM;
    const __half* Bg = g_Gf + (size_t)bn * BN * KDIM;

    float acc[4][8][4];
    #pragma unroll
    for (int a = 0; a < 4; ++a)
        #pragma unroll
        for (int b = 0; b < 8; ++b)
            #pragma unroll
            for (int c = 0; c < 4; ++c) acc[a][b][c] = 0.f;

    auto loadStage = [&](int ch, int st) {
        const uint32_t sb = sm0 + (uint32_t)st * STAGE_BYTES;
        const int kc = ch * BK;
        #pragma unroll
        for (int t = 0; t < 8; ++t) {             // A: 1024 x 16B chunks
            int q = tid + t * 128;
            int row = q >> 3, c = q & 7;
            cpa16(sb + S_A + swz(row, c * 16),
                  (const char*)(Ax + (size_t)row * KDIM + kc) + c * 16);
        }
        #pragma unroll
        for (int t = 0; t < 8; ++t) {             // B: 1024 x 16B chunks
            int q = tid + t * 128;
            int row = q >> 3, c = q & 7;
            cpa16(sb + S_B + swz(row, c * 16),
                  (const char*)(Bg + (size_t)row * KDIM + kc) + c * 16);
        }
    };

    // prologue: stages 0,1
    loadStage(0, 0);
    asm volatile("cp.async.commit_group;");
    loadStage(1, 1);
    asm volatile("cp.async.commit_group;");

    int cur = 0, nxt = 2;
    for (int ch = 0; ch < NCH; ++ch) {
        asm volatile("cp.async.wait_group 1;");
        __syncthreads();
        if (ch + 2 < NCH) loadStage(ch + 2, nxt);
        asm volatile("cp.async.commit_group;");

        const uint32_t sb = sm0 + (uint32_t)cur * STAGE_BYTES;
        cur = (cur == 2) ? 0 : cur + 1;
        nxt = (nxt == 2) ? 0 : nxt + 1;

        #pragma unroll
        for (int kk = 0; kk < BK; kk += 16) {
            uint32_t av[4][4];
            #pragma unroll
            for (int im = 0; im < 4; ++im) {
                int row = wm * 64 + im * 16 + (lane & 15);
                int byte = kk * 2 + ((lane >> 4) << 4);
                ldmx4(av[im], sb + S_A + swz(row, byte));
            }
            #pragma unroll
            for (int jp = 0; jp < 4; ++jp) {      // each ldmatrix.x4 covers 2 jn octets
                int nrow = wn * 64 + (jp * 2 + (lane >> 4)) * 8 + (lane & 7);
                int byte = kk * 2 + (((lane >> 3) & 1) << 4);
                uint32_t bv[4];
                ldmx4(bv, sb + S_B + swz(nrow, byte));
                #pragma unroll
                for (int im = 0; im < 4; ++im) {
                    mma16816(acc[im][jp * 2],     av[im], bv[0], bv[1]);
                    mma16816(acc[im][jp * 2 + 1], av[im], bv[2], bv[3]);
                }
            }
        }
    }

    // ---- epilogue: add bias, store fp32 ----
    #pragma unroll
    for (int im = 0; im < 4; ++im) {
        int r0 = bm * BM + wm * 64 + im * 16 + (lane >> 2);
        #pragma unroll
        for (int jn = 0; jn < 8; ++jn) {
            int cb = bn * BN + wn * 64 + jn * 8 + (lane & 3) * 2;
            float b0 = bias[cb], b1 = bias[cb + 1];
            float2 v0, v1;
            v0.x = acc[im][jn][0] + b0; v0.y = acc[im][jn][1] + b1;
            v1.x = acc[im][jn][2] + b0; v1.y = acc[im][jn][3] + b1;
            *reinterpret_cast<float2*>(C + (size_t)r0 * NDIM + cb) = v0;
            *reinterpret_cast<float2*>(C + (size_t)(r0 + 8) * NDIM + cb) = v1;
        }
    }
}

// ---------------- launch ----------------
extern "C" void kernel_launch(void* const* d_in, const int* in_sizes, int n_in,
                              void* d_out, int out_size) {
    const float* x     = (const float*)d_in[0];
    const float* core0 = (const float*)d_in[1];
    const float* core1 = (const float*)d_in[2];
    const float* core2 = (const float*)d_in[3];
    const float* bias  = (const float*)d_in[4];
    float* out = (float*)d_out;

    build_T<<<dim3(256, 4), 256>>>(core0, core1);
    build_G<<<dim3(256, 2), 256>>>(core2);
    conv_x<<<(MDIM * KDIM / 4) / 256, 256>>>(x);

    cudaFuncSetAttribute(gemm_pipe, cudaFuncAttributeMaxDynamicSharedMemorySize, SMEM_BYTES);
    dim3 grid(NDIM / BN, MDIM / BM);     // (32, 64), x-fastest keeps G hot in L2
    gemm_pipe<<<grid, 128, SMEM_BYTES>>>(bias, out);
}